// round 12
// baseline (speedup 1.0000x reference)
#include <cuda_runtime.h>
#include <cstdint>

// naivePC: DP over (k,m) lattice, K=8, N=20.
// Transformed DP: S~(k,m) = S(k,m)/P_k[m], P_k[m] = prod_{j=k+1..m} w0_k[j], P_k[k]=1.
//   S~(k,m) = S~(k,m-1) + g_k[m]*x_{m-1}*S~(k-1,m-1),  g_k[m]=w1_k[m]*P_{k-1}[m-1]/P_k[m]
// => one predicated FFMA per (row, level, column). Output = S~(8,20)*P_8[20].
// Leaf/k2 collapse: S~2(m) = cc (constant) for m>=mstart=p2+1,
//   cc = v*invP2[mstart], v = w1_2[mstart]*wsm[p2][p1] (or 1 if bits 0,1 set);
//   k=3 update: @(Q bit) S~3 += g3t[m]*cc, Q = mask & (~0<<mstart).

#define NCOL 20
#define KMAX 8
#define TILES 2
#define THREADS 128
#define WARPS (THREADS / 32)
#define ROWS_PER_BLOCK (THREADS * TILES)   // 256

__device__ float  g_wsm[21 * 32];
__device__ float2 g_w01[9 * 21];
__device__ float  g_invP2[22];
__device__ float4 g_gA[21];    // (g3t, g4, g5, g6)
__device__ float2 g_gB[21];    // (g7, g8)
__device__ float  g_scale;     // P_8[20]
__device__ int    g_elem4;

__global__ void prep_kernel(const unsigned char* __restrict__ xb,
                            const float* __restrict__ Wleaf,
                            const float* __restrict__ W2)
{
    __shared__ float sP[9][21];   // P_k[m], k=2..8

    const int tid  = threadIdx.x;
    const int lane = tid & 31;
    const int wid  = tid >> 5;

    // ---- wsm: one warp per m, shuffle reductions ----
    if (wid < 21) {
        int m = wid;
        float v = (lane < m) ? Wleaf[m * 20 + lane] : -1e30f;
        float mx = v;
        #pragma unroll
        for (int o = 16; o > 0; o >>= 1) mx = fmaxf(mx, __shfl_xor_sync(0xFFFFFFFFu, mx, o));
        float e = (lane < m) ? expf(v - mx) : 0.0f;
        float Z = e;
        #pragma unroll
        for (int o = 16; o > 0; o >>= 1) Z += __shfl_xor_sync(0xFFFFFFFFu, Z, o);
        float inv = (m > 0) ? (1.0f / Z) : 0.0f;
        g_wsm[m * 32 + lane] = e * inv;
    }
    // ---- w2 softmax: 189 pairs ----
    if (tid < 9 * 21) {
        float a = W2[tid * 2 + 0];
        float b = W2[tid * 2 + 1];
        float mx = fmaxf(a, b);
        float e0 = expf(a - mx), e1 = expf(b - mx);
        float inv = 1.0f / (e0 + e1);
        g_w01[tid] = make_float2(e0 * inv, e1 * inv);
    }
    // ---- dtype detection (warp 21) ----
    if (wid == 21) {
        unsigned w = reinterpret_cast<const unsigned*>(xb)[lane];
        unsigned gt1 = __ballot_sync(0xFFFFFFFFu, (w & 0xFEFEFEFEu) != 0u);
        unsigned hi  = __ballot_sync(0xFFFFFFFFu, (w & 0xFFFFFF00u) != 0u);
        if (lane == 0) g_elem4 = (gt1 != 0u || hi == 0u) ? 1 : 0;
    }
    __syncthreads();

    // ---- decay prefix products P_k[m] ----
    if (tid >= 2 && tid <= 8) {
        int k = tid;
        float p = 1.0f;
        for (int m = k; m <= 20; m++) {
            if (m > k) p *= g_w01[k * 21 + m].x;
            sP[k][m] = p;
        }
    }
    __syncthreads();

    // ---- transformed couplings ----
    if (tid < 21) {
        int m = tid;
        g_invP2[m] = (m >= 2) ? (1.0f / sP[2][m]) : 0.0f;
        float4 a;
        float2 b;
        a.x = (m >= 4) ? g_w01[3 * 21 + m].y * sP[2][m - 1] / sP[3][m] : 0.0f;
        a.y = (m >= 5) ? g_w01[4 * 21 + m].y * sP[3][m - 1] / sP[4][m] : 0.0f;
        a.z = (m >= 6) ? g_w01[5 * 21 + m].y * sP[4][m - 1] / sP[5][m] : 0.0f;
        a.w = (m >= 7) ? g_w01[6 * 21 + m].y * sP[5][m - 1] / sP[6][m] : 0.0f;
        b.x = (m >= 8) ? g_w01[7 * 21 + m].y * sP[6][m - 1] / sP[7][m] : 0.0f;
        b.y = (m >= 9) ? g_w01[8 * 21 + m].y * sP[7][m - 1] / sP[8][m] : 0.0f;
        g_gA[m] = a;
        g_gB[m] = b;
    }
    if (tid == 21) { g_invP2[21] = 0.0f; g_scale = sP[8][20]; }
}

__global__ __launch_bounds__(THREADS, 14)
void pc_kernel(const unsigned char* __restrict__ xb,
               float* __restrict__ out,
               int B)
{
    __shared__ unsigned s_bal[WARPS][TILES][24];   // per-tile buffers: no false dependency

    const int tid    = threadIdx.x;
    const int lane   = tid & 31;
    const int warpId = tid >> 5;
    const int elem4  = g_elem4;

    const int warpRow = blockIdx.x * ROWS_PER_BLOCK + warpId * (32 * TILES);

    // ---- 1. masks: both tiles' load+ballot phases, then one syncwarp, then extracts ----
    unsigned mask[TILES];

    if (elem4) {
        const unsigned* xw = reinterpret_cast<const unsigned*>(xb);
        const int wTotal = B * 20;
        #pragma unroll
        for (int t = 0; t < TILES; t++) {
            const int tileRow = warpRow + t * 32;
            const int wbase = tileRow * 20;
            unsigned w[20];
            if (tileRow + 32 <= B) {
                #pragma unroll
                for (int j = 0; j < 20; j++)
                    w[j] = xw[wbase + j * 32 + lane];           // front-batched MLP=20
            } else {
                #pragma unroll
                for (int j = 0; j < 20; j++) {
                    int idx = wbase + j * 32 + lane;
                    w[j] = (idx < wTotal) ? xw[idx] : 0u;
                }
            }
            #pragma unroll
            for (int j = 0; j < 20; j++) {
                unsigned bal = __ballot_sync(0xFFFFFFFFu, w[j] != 0u);
                if (lane == 0) s_bal[warpId][t][j] = bal;
            }
        }
        __syncwarp();
        #pragma unroll
        for (int t = 0; t < TILES; t++) {
            int pos = 20 * lane;
            unsigned lo = s_bal[warpId][t][pos >> 5];
            unsigned hi = s_bal[warpId][t][(pos >> 5) + 1];
            mask[t] = __funnelshift_r(lo, hi, pos & 31) & 0xFFFFFu;
        }
    } else {
        #pragma unroll
        for (int t = 0; t < TILES; t++) {
            int row = warpRow + t * 32 + lane;
            unsigned mres = 0;
            if (row < B) {
                const unsigned* p = reinterpret_cast<const unsigned*>(xb + (size_t)row * 20);
                #pragma unroll
                for (int j = 0; j < 5; j++) {
                    unsigned b = p[j] & 0x01010101u;
                    unsigned nib = ((b * 0x01020408u) >> 24) & 0xFu;
                    mres |= nib << (4 * j);
                }
            }
            mask[t] = mres;
        }
    }

    // ---- 2. per-row leaf/k2 collapse (__ldg gathers; no smem, no block sync) ----
    float cc[TILES];
    unsigned Q[TILES];
    #pragma unroll
    for (int r = 0; r < TILES; r++) {
        unsigned M = mask[r];
        unsigned rem = M & (M - 1);
        int mst;
        float v;
        if (rem != 0u) {
            int p1 = __ffs(M) - 1;
            int p2 = __ffs(rem) - 1;
            mst = p2 + 1;
            bool pf2 = (M & 3u) == 3u;
            v = pf2 ? 1.0f : __ldg(&((const float*)g_w01)[(2 * 21 + mst) * 2 + 1])
                           * __ldg(&g_wsm[p2 * 32 + p1]);
        } else {
            mst = 21;
            v = 0.0f;
        }
        cc[r] = v * __ldg(&g_invP2[mst]);
        Q[r]  = M & (0xFFFFFFFFu << mst);
    }
    const float scale = __ldg(&g_scale);

    // ---- 3. column-sweep DP: tables via uniform __ldg (compile-time m) ----
    float S[TILES][KMAX - 2];   // S[r][k-3] = S~(k,.)
    #pragma unroll
    for (int r = 0; r < TILES; r++)
        #pragma unroll
        for (int k = 0; k < KMAX - 2; k++) S[r][k] = 0.0f;

    #pragma unroll
    for (int m = 1; m <= NCOL; m++) {
        const unsigned mbit = 1u << (m - 1);
        const float4 ga = __ldg(&g_gA[m]);
        const float2 gb = __ldg(&g_gB[m]);

        #pragma unroll
        for (int k = KMAX; k >= 4; k--) {
            if (k > m) continue;                    // folds at compile time
            if (k == m) {
                const unsigned km = (1u << k) - 1u;
                #pragma unroll
                for (int r = 0; r < TILES; r++)
                    S[r][k - 3] = ((mask[r] & km) == km) ? 1.0f : 0.0f;
            } else {
                const float g = (k == 4) ? ga.y : (k == 5) ? ga.z : (k == 6) ? ga.w
                              : (k == 7) ? gb.x : gb.y;
                #pragma unroll
                for (int r = 0; r < TILES; r++)
                    S[r][k - 3] = (mask[r] & mbit) ? fmaf(g, S[r][k - 4], S[r][k - 3])
                                                   : S[r][k - 3];
            }
        }
        if (m == 3) {
            #pragma unroll
            for (int r = 0; r < TILES; r++)
                S[r][0] = ((mask[r] & 7u) == 7u) ? 1.0f : 0.0f;
        } else if (m > 3) {
            #pragma unroll
            for (int r = 0; r < TILES; r++)
                S[r][0] = (Q[r] & mbit) ? fmaf(ga.x, cc[r], S[r][0]) : S[r][0];
        }
    }

    // ---- coalesced store ----
    #pragma unroll
    for (int t = 0; t < TILES; t++) {
        int row = warpRow + t * 32 + lane;
        if (row < B) out[row] = S[t][KMAX - 3] * scale;
    }
}

extern "C" void kernel_launch(void* const* d_in, const int* in_sizes, int n_in,
                              void* d_out, int out_size)
{
    const unsigned char* x = (const unsigned char*)d_in[0];
    const float* Wleaf = (const float*)d_in[1];
    const float* W2 = (const float*)d_in[2];
    float* out = (float*)d_out;

    const int B = in_sizes[0] / NCOL;
    const int blocks = (B + ROWS_PER_BLOCK - 1) / ROWS_PER_BLOCK;

    prep_kernel<<<1, 736>>>(x, Wleaf, W2);
    pc_kernel<<<blocks, THREADS>>>(x, out, B);
}

// round 13
// speedup vs baseline: 1.0022x; 1.0022x over previous
#include <cuda_runtime.h>
#include <cstdint>

// naivePC: DP over (k,m) lattice, K=8, N=20.
// Transformed DP: S~(k,m) = S(k,m)/P_k[m], P_k[m] = prod_{j=k+1..m} w0_k[j], P_k[k]=1.
//   S~(k,m) = S~(k,m-1) + g_k[m]*x_{m-1}*S~(k-1,m-1),  g_k[m]=w1_k[m]*P_{k-1}[m-1]/P_k[m]
// => one predicated FFMA per (row, level, column). Output = S~(8,20)*P_8[20].
// Leaf/k2 collapse: S~2(m) = cc (constant) for m>=mstart=p2+1,
//   cc = v*invP2[mstart], v = w1_2[mstart]*wsm[p2][p1] (or 1 if bits 0,1 set);
//   k=3 update: @(Q bit) S~3 += g3t[m]*cc, Q = mask & (~0<<mstart).

#define NCOL 20
#define KMAX 8
#define TILES 4
#define THREADS 128
#define WARPS (THREADS / 32)
#define ROWS_PER_BLOCK (THREADS * TILES)   // 512

__device__ float  g_wsm[21 * 32];
__device__ float2 g_w01[9 * 21];
__device__ float  g_invP2[22];
__device__ float4 g_gA[21];    // (g3t, g4, g5, g6)
__device__ float2 g_gB[21];    // (g7, g8)
__device__ float  g_scale;     // P_8[20]
__device__ int    g_elem4;

__global__ void prep_kernel(const unsigned char* __restrict__ xb,
                            const float* __restrict__ Wleaf,
                            const float* __restrict__ W2)
{
    __shared__ float sP[9][21];   // P_k[m], k=2..8

    const int tid  = threadIdx.x;
    const int lane = tid & 31;
    const int wid  = tid >> 5;

    // ---- wsm: one warp per m, shuffle reductions ----
    if (wid < 21) {
        int m = wid;
        float v = (lane < m) ? Wleaf[m * 20 + lane] : -1e30f;
        float mx = v;
        #pragma unroll
        for (int o = 16; o > 0; o >>= 1) mx = fmaxf(mx, __shfl_xor_sync(0xFFFFFFFFu, mx, o));
        float e = (lane < m) ? expf(v - mx) : 0.0f;
        float Z = e;
        #pragma unroll
        for (int o = 16; o > 0; o >>= 1) Z += __shfl_xor_sync(0xFFFFFFFFu, Z, o);
        float inv = (m > 0) ? (1.0f / Z) : 0.0f;
        g_wsm[m * 32 + lane] = e * inv;
    }
    // ---- w2 softmax: 189 pairs ----
    if (tid < 9 * 21) {
        float a = W2[tid * 2 + 0];
        float b = W2[tid * 2 + 1];
        float mx = fmaxf(a, b);
        float e0 = expf(a - mx), e1 = expf(b - mx);
        float inv = 1.0f / (e0 + e1);
        g_w01[tid] = make_float2(e0 * inv, e1 * inv);
    }
    // ---- dtype detection (warp 21) ----
    if (wid == 21) {
        unsigned w = reinterpret_cast<const unsigned*>(xb)[lane];
        unsigned gt1 = __ballot_sync(0xFFFFFFFFu, (w & 0xFEFEFEFEu) != 0u);
        unsigned hi  = __ballot_sync(0xFFFFFFFFu, (w & 0xFFFFFF00u) != 0u);
        if (lane == 0) g_elem4 = (gt1 != 0u || hi == 0u) ? 1 : 0;
    }
    __syncthreads();

    // ---- decay prefix products P_k[m] ----
    if (tid >= 2 && tid <= 8) {
        int k = tid;
        float p = 1.0f;
        for (int m = k; m <= 20; m++) {
            if (m > k) p *= g_w01[k * 21 + m].x;
            sP[k][m] = p;
        }
    }
    __syncthreads();

    // ---- transformed couplings ----
    if (tid < 21) {
        int m = tid;
        g_invP2[m] = (m >= 2) ? (1.0f / sP[2][m]) : 0.0f;
        float4 a;
        float2 b;
        a.x = (m >= 4) ? g_w01[3 * 21 + m].y * sP[2][m - 1] / sP[3][m] : 0.0f;
        a.y = (m >= 5) ? g_w01[4 * 21 + m].y * sP[3][m - 1] / sP[4][m] : 0.0f;
        a.z = (m >= 6) ? g_w01[5 * 21 + m].y * sP[4][m - 1] / sP[5][m] : 0.0f;
        a.w = (m >= 7) ? g_w01[6 * 21 + m].y * sP[5][m - 1] / sP[6][m] : 0.0f;
        b.x = (m >= 8) ? g_w01[7 * 21 + m].y * sP[6][m - 1] / sP[7][m] : 0.0f;
        b.y = (m >= 9) ? g_w01[8 * 21 + m].y * sP[7][m - 1] / sP[8][m] : 0.0f;
        g_gA[m] = a;
        g_gB[m] = b;
    }
    if (tid == 21) { g_invP2[21] = 0.0f; g_scale = sP[8][20]; }
}

__global__ __launch_bounds__(THREADS, 7)
void pc_kernel(const unsigned char* __restrict__ xb,
               float* __restrict__ out,
               int B)
{
    __shared__ unsigned s_bal[WARPS][TILES][24];   // per-tile buffers: no WAR hazards

    const int tid    = threadIdx.x;
    const int lane   = tid & 31;
    const int warpId = tid >> 5;
    const int elem4  = g_elem4;

    const int warpRow = blockIdx.x * ROWS_PER_BLOCK + warpId * (32 * TILES);

    // ---- 1. masks: 2-stage software pipeline (load tile t+1 before ballots of t) ----
    unsigned mask[TILES];

    if (elem4) {
        const unsigned* xw = reinterpret_cast<const unsigned*>(xb);
        const int wTotal = B * 20;
        unsigned w[2][20];

        // prologue: load tile 0
        {
            const int wbase = warpRow * 20;
            if (warpRow + 32 <= B) {
                #pragma unroll
                for (int j = 0; j < 20; j++) w[0][j] = xw[wbase + j * 32 + lane];
            } else {
                #pragma unroll
                for (int j = 0; j < 20; j++) {
                    int idx = wbase + j * 32 + lane;
                    w[0][j] = (idx < wTotal) ? xw[idx] : 0u;
                }
            }
        }
        #pragma unroll
        for (int t = 0; t < TILES; t++) {
            // issue next tile's loads before this tile's ballot chain
            if (t + 1 < TILES) {
                const int tileRow = warpRow + (t + 1) * 32;
                const int wbase = tileRow * 20;
                if (tileRow + 32 <= B) {
                    #pragma unroll
                    for (int j = 0; j < 20; j++) w[(t + 1) & 1][j] = xw[wbase + j * 32 + lane];
                } else {
                    #pragma unroll
                    for (int j = 0; j < 20; j++) {
                        int idx = wbase + j * 32 + lane;
                        w[(t + 1) & 1][j] = (idx < wTotal) ? xw[idx] : 0u;
                    }
                }
            }
            #pragma unroll
            for (int j = 0; j < 20; j++) {
                unsigned bal = __ballot_sync(0xFFFFFFFFu, w[t & 1][j] != 0u);
                if (lane == 0) s_bal[warpId][t][j] = bal;
            }
        }
        __syncwarp();
        #pragma unroll
        for (int t = 0; t < TILES; t++) {
            int pos = 20 * lane;
            unsigned lo = s_bal[warpId][t][pos >> 5];
            unsigned hi = s_bal[warpId][t][(pos >> 5) + 1];
            mask[t] = __funnelshift_r(lo, hi, pos & 31) & 0xFFFFFu;
        }
    } else {
        #pragma unroll
        for (int t = 0; t < TILES; t++) {
            int row = warpRow + t * 32 + lane;
            unsigned mres = 0;
            if (row < B) {
                const unsigned* p = reinterpret_cast<const unsigned*>(xb + (size_t)row * 20);
                #pragma unroll
                for (int j = 0; j < 5; j++) {
                    unsigned b = p[j] & 0x01010101u;
                    unsigned nib = ((b * 0x01020408u) >> 24) & 0xFu;
                    mres |= nib << (4 * j);
                }
            }
            mask[t] = mres;
        }
    }

    // ---- 2. per-row leaf/k2 collapse (__ldg gathers; no block sync anywhere) ----
    float cc[TILES];
    unsigned Q[TILES];
    #pragma unroll
    for (int r = 0; r < TILES; r++) {
        unsigned M = mask[r];
        unsigned rem = M & (M - 1);
        int mst;
        float v;
        if (rem != 0u) {
            int p1 = __ffs(M) - 1;
            int p2 = __ffs(rem) - 1;
            mst = p2 + 1;
            bool pf2 = (M & 3u) == 3u;
            v = pf2 ? 1.0f : __ldg(&((const float*)g_w01)[(2 * 21 + mst) * 2 + 1])
                           * __ldg(&g_wsm[p2 * 32 + p1]);
        } else {
            mst = 21;
            v = 0.0f;
        }
        cc[r] = v * __ldg(&g_invP2[mst]);
        Q[r]  = M & (0xFFFFFFFFu << mst);
    }
    const float scale = __ldg(&g_scale);

    // ---- 3. column-sweep DP: 1 predicated FFMA per (row, level, column) ----
    float S[TILES][KMAX - 2];   // S[r][k-3] = S~(k,.)
    #pragma unroll
    for (int r = 0; r < TILES; r++)
        #pragma unroll
        for (int k = 0; k < KMAX - 2; k++) S[r][k] = 0.0f;

    #pragma unroll
    for (int m = 1; m <= NCOL; m++) {
        const unsigned mbit = 1u << (m - 1);
        const float4 ga = __ldg(&g_gA[m]);
        const float2 gb = __ldg(&g_gB[m]);

        #pragma unroll
        for (int k = KMAX; k >= 4; k--) {
            if (k > m) continue;                    // folds at compile time
            if (k == m) {
                const unsigned km = (1u << k) - 1u;
                #pragma unroll
                for (int r = 0; r < TILES; r++)
                    S[r][k - 3] = ((mask[r] & km) == km) ? 1.0f : 0.0f;
            } else {
                const float g = (k == 4) ? ga.y : (k == 5) ? ga.z : (k == 6) ? ga.w
                              : (k == 7) ? gb.x : gb.y;
                #pragma unroll
                for (int r = 0; r < TILES; r++)
                    S[r][k - 3] = (mask[r] & mbit) ? fmaf(g, S[r][k - 4], S[r][k - 3])
                                                   : S[r][k - 3];
            }
        }
        if (m == 3) {
            #pragma unroll
            for (int r = 0; r < TILES; r++)
                S[r][0] = ((mask[r] & 7u) == 7u) ? 1.0f : 0.0f;
        } else if (m > 3) {
            #pragma unroll
            for (int r = 0; r < TILES; r++)
                S[r][0] = (Q[r] & mbit) ? fmaf(ga.x, cc[r], S[r][0]) : S[r][0];
        }
    }

    // ---- coalesced store ----
    #pragma unroll
    for (int t = 0; t < TILES; t++) {
        int row = warpRow + t * 32 + lane;
        if (row < B) out[row] = S[t][KMAX - 3] * scale;
    }
}

extern "C" void kernel_launch(void* const* d_in, const int* in_sizes, int n_in,
                              void* d_out, int out_size)
{
    const unsigned char* x = (const unsigned char*)d_in[0];
    const float* Wleaf = (const float*)d_in[1];
    const float* W2 = (const float*)d_in[2];
    float* out = (float*)d_out;

    const int B = in_sizes[0] / NCOL;
    const int blocks = (B + ROWS_PER_BLOCK - 1) / ROWS_PER_BLOCK;

    prep_kernel<<<1, 736>>>(x, Wleaf, W2);
    pc_kernel<<<blocks, THREADS>>>(x, out, B);
}